// round 4
// baseline (speedup 1.0000x reference)
#include <cuda_runtime.h>
#include <cuda_fp16.h>
#include <cstdint>

#define MM 4096
#define KK 4096
#define NN 12288
#define GS 128
#define GG (KK / GS)

#define BM 128
#define BN 128
#define BK 32
#define LDA 40   // 32 + 8 halves pad
#define LDB 136  // 128 + 8 halves pad

// Scratch (device-global statics are the sanctioned no-alloc workaround)
__device__ __half g_W[(size_t)KK * NN];   // dequantized weights, row-major [K, N]
__device__ __half g_A[(size_t)MM * KK];   // permuted activations, row-major [M, K]
__device__ int    g_perm[KK];
__device__ int    g_f32;                  // 1 if fp16 tensors arrive upcast to fp32

// ---------------------------------------------------------------------------
// Dtype probe: q_scale_max true values lie in (0, 1/256]. If the buffer is
// genuinely fp32, all reads land in (1e-8, 0.004). If it is really fp16 data,
// the fp32 reinterpretation has exponent ~40 -> ~1e-26 -> probe fails.
__global__ void probe_dtype(const void* __restrict__ qsm) {
    if (threadIdx.x == 0) {
        const float* f = (const float*)qsm;   // 16 floats = 64B = full 32-half buffer
        int ok = 1;
#pragma unroll
        for (int i = 0; i < 16; ++i) {
            float v = f[i];
            if (!(v > 1e-8f && v < 0.004f)) ok = 0;
        }
        g_f32 = ok;
    }
}

// perm = argsort(q_invperm)  (inverse permutation via scatter)
__global__ void build_perm(const int* __restrict__ invperm) {
    int j = blockIdx.x * blockDim.x + threadIdx.x;
    if (j < KK) g_perm[invperm[j]] = j;
}

// A[m, k] = x[m, perm[k]] — coalesced writes, L2-resident scattered reads
__global__ void permute_act(const void* __restrict__ inp) {
    int idx = blockIdx.x * blockDim.x + threadIdx.x;   // m*K + k
    int k = idx & (KK - 1);
    int m = idx >> 12;                                  // K = 2^12
    int src = (m << 12) + g_perm[k];
    __half v;
    if (g_f32) v = __float2half(((const float*)inp)[src]);
    else       v = ((const __half*)inp)[src];
    g_A[idx] = v;
}

// W[k, n] = (code(k,n) - 8) * (scode(g,n)+1)^2 * scale_max[g]
__global__ void dequant_w(const int* __restrict__ qw, const int* __restrict__ qs,
                          const void* __restrict__ qsm) {
    int idx = blockIdx.x * blockDim.x + threadIdx.x;   // kk*N + n, kk in [0, K/8)
    int n  = idx % NN;
    int kk = idx / NN;
    int w  = qw[idx];
    int g  = kk >> 4;                                   // (kk*8)/128
    float smax = g_f32 ? ((const float*)qsm)[g]
                       : __half2float(((const __half*)qsm)[g]);
    int sq = qs[g * (NN / 8) + (n >> 3)];
    int scode = (sq >> ((n & 7) * 4)) & 0xF;
    float scale = (float)((scode + 1) * (scode + 1)) * smax;
    __half* dst = g_W + (size_t)(kk * 8) * NN + n;
#pragma unroll
    for (int i = 0; i < 8; ++i) {
        int code = (w >> (i * 4)) & 0xF;
        dst[(size_t)i * NN] = __float2half((float)(code - 8) * scale);
    }
}

// ---------------------------------------------------------------------------
// GEMM: C[M,N] = A[M,K] * W[K,N] + bias. 128x128x32 tiles, double-buffered
// cp.async, ldmatrix + mma.sync.m16n8k16 (f16 in, f32 accum).
__global__ __launch_bounds__(256) void gemm_kernel(void* __restrict__ outv,
                                                   const void* __restrict__ biasv) {
    __shared__ __half As[2][BM * LDA];
    __shared__ __half Bs[2][BK * LDB];

    const int tid  = threadIdx.x;
    const int lane = tid & 31;
    const int warp = tid >> 5;
    const int warp_m = warp >> 1;   // 0..3  (32 rows each)
    const int warp_n = warp & 1;    // 0..1  (64 cols each)
    const int f32mode = g_f32;

    const int m0 = blockIdx.y * BM;
    const int n0 = blockIdx.x * BN;

    const __half* Ag = g_A + (size_t)m0 * KK;
    const __half* Bg = g_W + n0;

    float acc[2][8][4];
#pragma unroll
    for (int i = 0; i < 2; ++i)
#pragma unroll
        for (int j = 0; j < 8; ++j)
#pragma unroll
            for (int c = 0; c < 4; ++c) acc[i][j][c] = 0.f;

    auto load_tile = [&](int kt, int buf) {
        int k0 = kt * BK;
#pragma unroll
        for (int i = 0; i < 2; ++i) {
            int c   = tid + i * 256;
            int row = c >> 2;
            int col = (c & 3) << 3;
            const __half* src = Ag + (size_t)row * KK + k0 + col;
            uint32_t dst = (uint32_t)__cvta_generic_to_shared(&As[buf][row * LDA + col]);
            asm volatile("cp.async.cg.shared.global [%0], [%1], 16;\n" :: "r"(dst), "l"(src));
        }
#pragma unroll
        for (int i = 0; i < 2; ++i) {
            int c   = tid + i * 256;
            int row = c >> 4;
            int col = (c & 15) << 3;
            const __half* src = Bg + (size_t)(k0 + row) * NN + col;
            uint32_t dst = (uint32_t)__cvta_generic_to_shared(&Bs[buf][row * LDB + col]);
            asm volatile("cp.async.cg.shared.global [%0], [%1], 16;\n" :: "r"(dst), "l"(src));
        }
    };

    load_tile(0, 0);
    asm volatile("cp.async.commit_group;\n" ::: "memory");

    const int KT = KK / BK;   // 128
    int buf = 0;
    for (int kt = 0; kt < KT; ++kt) {
        if (kt + 1 < KT) {
            load_tile(kt + 1, buf ^ 1);
            asm volatile("cp.async.commit_group;\n" ::: "memory");
            asm volatile("cp.async.wait_group 1;\n" ::: "memory");
        } else {
            asm volatile("cp.async.wait_group 0;\n" ::: "memory");
        }
        __syncthreads();

#pragma unroll
        for (int ks = 0; ks < 2; ++ks) {
            uint32_t a[2][4], b[8][2];
#pragma unroll
            for (int mi = 0; mi < 2; ++mi) {
                int row = warp_m * 32 + mi * 16 + (lane & 15);
                int col = ks * 16 + ((lane >> 4) << 3);
                uint32_t addr = (uint32_t)__cvta_generic_to_shared(&As[buf][row * LDA + col]);
                asm volatile(
                    "ldmatrix.sync.aligned.m8n8.x4.shared.b16 {%0,%1,%2,%3}, [%4];\n"
                    : "=r"(a[mi][0]), "=r"(a[mi][1]), "=r"(a[mi][2]), "=r"(a[mi][3])
                    : "r"(addr));
            }
#pragma unroll
            for (int nb = 0; nb < 4; ++nb) {
                int row = ks * 16 + (lane & 15);
                int col = warp_n * 64 + nb * 16 + ((lane >> 4) << 3);
                uint32_t addr = (uint32_t)__cvta_generic_to_shared(&Bs[buf][row * LDB + col]);
                asm volatile(
                    "ldmatrix.sync.aligned.m8n8.x4.trans.shared.b16 {%0,%1,%2,%3}, [%4];\n"
                    : "=r"(b[2 * nb][0]), "=r"(b[2 * nb][1]),
                      "=r"(b[2 * nb + 1][0]), "=r"(b[2 * nb + 1][1])
                    : "r"(addr));
            }
#pragma unroll
            for (int mi = 0; mi < 2; ++mi)
#pragma unroll
                for (int ni = 0; ni < 8; ++ni) {
                    asm volatile(
                        "mma.sync.aligned.m16n8k16.row.col.f32.f16.f16.f32 "
                        "{%0,%1,%2,%3}, {%4,%5,%6,%7}, {%8,%9}, {%0,%1,%2,%3};\n"
                        : "+f"(acc[mi][ni][0]), "+f"(acc[mi][ni][1]),
                          "+f"(acc[mi][ni][2]), "+f"(acc[mi][ni][3])
                        : "r"(a[mi][0]), "r"(a[mi][1]), "r"(a[mi][2]), "r"(a[mi][3]),
                          "r"(b[ni][0]), "r"(b[ni][1]));
                }
        }
        __syncthreads();
        buf ^= 1;
    }

    // Epilogue. C frag: (c0,c1)->row lane/4, (c2,c3)->row+8; cols (lane%4)*2,+1
#pragma unroll
    for (int mi = 0; mi < 2; ++mi) {
#pragma unroll
        for (int ni = 0; ni < 8; ++ni) {
            int row0 = m0 + warp_m * 32 + mi * 16 + (lane >> 2);
            int col  = n0 + warp_n * 64 + ni * 8 + (lane & 3) * 2;
            float bx, by;
            if (f32mode) {
                const float* bp = (const float*)biasv + col;
                bx = bp[0]; by = bp[1];
            } else {
                __half2 bv = *reinterpret_cast<const __half2*>((const __half*)biasv + col);
                float2 b2 = __half22float2(bv);
                bx = b2.x; by = b2.y;
            }
            float v00 = acc[mi][ni][0] + bx, v01 = acc[mi][ni][1] + by;
            float v10 = acc[mi][ni][2] + bx, v11 = acc[mi][ni][3] + by;
            if (f32mode) {
                float* op = (float*)outv;
                *reinterpret_cast<float2*>(&op[(size_t)row0 * NN + col]) =
                    make_float2(v00, v01);
                *reinterpret_cast<float2*>(&op[(size_t)(row0 + 8) * NN + col]) =
                    make_float2(v10, v11);
            } else {
                __half* op = (__half*)outv;
                *reinterpret_cast<__half2*>(&op[(size_t)row0 * NN + col]) =
                    __floats2half2_rn(v00, v01);
                *reinterpret_cast<__half2*>(&op[(size_t)(row0 + 8) * NN + col]) =
                    __floats2half2_rn(v10, v11);
            }
        }
    }
}

// ---------------------------------------------------------------------------
extern "C" void kernel_launch(void* const* d_in, const int* in_sizes, int n_in,
                              void* d_out, int out_size) {
    const void* input   = d_in[0];              // [M, K] fp16 (or fp32-upcast)
    const int*  qw      = (const int*)d_in[1];  // [K/8, N] int32
    const int*  qs      = (const int*)d_in[2];  // [G, N/8] int32
    const void* qsm     = d_in[3];              // [G] fp16 (or fp32-upcast)
    const int*  invperm = (const int*)d_in[4];  // [K] int32
    const void* bias    = d_in[5];              // [N] fp16 (or fp32-upcast)

    probe_dtype<<<1, 32>>>(qsm);
    build_perm<<<KK / 256, 256>>>(invperm);
    permute_act<<<(MM * KK) / 256, 256>>>(input);
    dequant_w<<<((KK / 8) * NN) / 256, 256>>>(qw, qs, qsm);

    dim3 grid(NN / BN, MM / BM);   // (96, 32)
    gemm_kernel<<<grid, 256>>>(d_out, bias);
}

// round 9
// speedup vs baseline: 1.4537x; 1.4537x over previous
#include <cuda_runtime.h>
#include <cuda_fp16.h>
#include <cstdint>

#define MM 4096
#define KK 4096
#define NN 12288
#define GG 32            // K / 128 groups
#define NCHUNK 64        // K / 64

#define BM 128
#define BN 256           // CTA tile (both paths)

// ---- dynamic smem layout (tcgen05 path) ----
#define B16_OFF  0                       // 3 x 32768 (fp16 B tiles, SW128)
#define A_OFF    (3*32768)               // 3 x 16384 (fp16 A tiles, SW128)
#define BPK_OFF  (A_OFF + 3*16384)       // 3 x 8192  (packed B words)
#define CTRL_OFF (BPK_OFF + 3*8192)      // tmem ptr + 3 mbarriers
#define SMEM_BYTES (CTRL_OFF + 64)       // 172096 B (fallback uses first ~38KB)

#define SWZ(x) ((x) ^ (((x) >> 3) & 0x70))
#define IDESC ((1u << 4) | ((BN / 8) << 17) | ((BM / 16) << 24))  // f32 acc, f16 in

// SW128 K-major smem descriptor (LBO=1, SBO=64, version=1, layout=2)
#define DESC_BASE ((uint64_t(2) << 61) | (uint64_t(1) << 46) | \
                   (uint64_t(64) << 32) | (uint64_t(1) << 16))
#define MAKE_DESC(a) (DESC_BASE | ((uint64_t)((a) >> 4) & 0x3FFF))

// fallback tile params (identical to proven R4 kernel)
#define FBK 32
#define LDA 40
#define LDB 136

// Scratch
__device__ __half g_W[(size_t)KK * NN];   // dequantized weights (fallback only)
__device__ __half g_A[(size_t)MM * KK];   // permuted activations [M, K]
__device__ float  g_S[(size_t)GG * NN];   // group scales (g, n)
__device__ int    g_perm[KK];
__device__ int    g_f32;                  // 1 if fp16 tensors arrive upcast to fp32
__device__ int    g_tc;                   // 1 if tcgen05 path is active on this GPU

// ---------------------------------------------------------------------------
__global__ void probe_arch() {
#ifdef __CUDA_ARCH_FEAT_SM103_ALL
    g_tc = 1;
#else
    g_tc = 0;
#endif
}

__global__ void probe_dtype(const void* __restrict__ qsm) {
    if (threadIdx.x == 0) {
        const float* f = (const float*)qsm;
        int ok = 1;
#pragma unroll
        for (int i = 0; i < 16; ++i) {
            float v = f[i];
            if (!(v > 1e-8f && v < 0.004f)) ok = 0;
        }
        g_f32 = ok;
    }
}

__global__ void build_perm(const int* __restrict__ invperm) {
    int j = blockIdx.x * blockDim.x + threadIdx.x;
    if (j < KK) g_perm[invperm[j]] = j;
}

__global__ void permute_act(const void* __restrict__ inp) {
    int idx = blockIdx.x * blockDim.x + threadIdx.x;
    int k = idx & (KK - 1);
    int m = idx >> 12;
    int src = (m << 12) + g_perm[k];
    __half v;
    if (g_f32) v = __float2half(((const float*)inp)[src]);
    else       v = ((const __half*)inp)[src];
    g_A[idx] = v;
}

// s[g, n] = (scode + 1)^2 * scale_max[g]
__global__ void build_scales(const int* __restrict__ qs, const void* __restrict__ qsm) {
    int idx = blockIdx.x * blockDim.x + threadIdx.x;
    int n = idx % NN;
    int g = idx / NN;
    float smax = g_f32 ? ((const float*)qsm)[g]
                       : __half2float(((const __half*)qsm)[g]);
    int sq = qs[g * (NN / 8) + (n >> 3)];
    int sc = (sq >> ((n & 7) * 4)) & 0xF;
    g_S[idx] = (float)((sc + 1) * (sc + 1)) * smax;
}

// Materialize fp16 W (fallback path only; early-exit when tcgen05 active)
__global__ void dequant_w(const int* __restrict__ qw) {
    if (g_tc) return;
    int idx = blockIdx.x * blockDim.x + threadIdx.x;   // kk*N + n
    int n  = idx % NN;
    int kk = idx / NN;
    int w  = qw[idx];
    int g  = kk >> 4;
    float scale = g_S[(size_t)g * NN + n];
    __half* dst = g_W + (size_t)(kk * 8) * NN + n;
#pragma unroll
    for (int i = 0; i < 8; ++i) {
        int code = (w >> (i * 4)) & 0xF;
        dst[(size_t)i * NN] = __float2half((float)(code - 8) * scale);
    }
}

// ---------------------------------------------------------------------------
__device__ __forceinline__ uint32_t elect_one() {
    uint32_t p;
    asm volatile("{.reg .pred p; elect.sync _|p, 0xFFFFFFFF; selp.b32 %0,1,0,p;}"
                 : "=r"(p));
    return p;
}
__device__ __forceinline__ void cp16(uint32_t dst, const void* src) {
    asm volatile("cp.async.cg.shared.global [%0], [%1], 16;\n" :: "r"(dst), "l"(src));
}
__device__ __forceinline__ void mbar_wait(uint32_t a, uint32_t par) {
    uint32_t done;
    asm volatile("{.reg .pred p; mbarrier.try_wait.parity.acquire.cta.shared::cta.b64 p, [%1], %2;"
                 " selp.b32 %0,1,0,p;}" : "=r"(done) : "r"(a), "r"(par) : "memory");
    if (!done) {
        asm volatile("{.reg .pred P1; WL_%=: mbarrier.try_wait.parity.acquire.cta.shared::cta.b64 P1, [%0], %1, 0x989680;"
                     " @P1 bra.uni WD_%=; bra.uni WL_%=; WD_%=:}"
                     :: "r"(a), "r"(par) : "memory");
    }
}

// ---------------------------------------------------------------------------
// One CTA = 128x256 output tile. Body selected per compile arch.
__global__ __launch_bounds__(256, 1) __cluster_dims__(1, 1, 1)
void gemm_tc(void* __restrict__ outv, const void* __restrict__ biasv,
             const int* __restrict__ qw) {
    extern __shared__ __align__(1024) char sm[];
    const int tid = threadIdx.x;
    const int bid = blockIdx.x;
    const int nb = bid % (NN / BN);
    const int mb = bid / (NN / BN);
    const int n0 = nb * BN;
    const int m0 = mb * BM;
    const int f32m = g_f32;

#ifdef __CUDA_ARCH_FEAT_SM103_ALL
    // ===================== tcgen05 fused-dequant path =====================
    const uint32_t smb = (uint32_t)__cvta_generic_to_shared(sm);
    if (tid < 32) {
        asm volatile("tcgen05.alloc.cta_group::1.sync.aligned.shared::cta.b32 [%0], %1;"
                     :: "r"(smb + CTRL_OFF), "r"(512u) : "memory");
        asm volatile("tcgen05.relinquish_alloc_permit.cta_group::1.sync.aligned;");
    }
    if (tid == 0) {
#pragma unroll
        for (int s = 0; s < 3; ++s)
            asm volatile("mbarrier.init.shared.b64 [%0], %1;"
                         :: "r"(smb + CTRL_OFF + 8 + s * 8), "r"(1u) : "memory");
    }
    __syncthreads();
    uint32_t tmem;
    asm volatile("ld.shared.b32 %0, [%1];" : "=r"(tmem) : "r"(smb + CTRL_OFF));

    const __half* Ag = g_A + (size_t)m0 * KK;
    const int*    Qg = qw + n0;

    auto ldchunk = [&](int k) {
        int b = k % 3;
        uint32_t Ab = smb + A_OFF + b * 16384;
#pragma unroll
        for (int i = 0; i < 4; ++i) {
            int idx = tid + i * 256;
            int row = idx >> 3, c16 = idx & 7;
            const void* src = Ag + (size_t)row * KK + k * 64 + c16 * 8;
            uint32_t off = (uint32_t)(row * 128 + c16 * 16);
            cp16(Ab + SWZ(off), src);
        }
        uint32_t Pb = smb + BPK_OFF + b * 8192;
#pragma unroll
        for (int i = 0; i < 2; ++i) {
            int idx = tid + i * 256;
            int r = idx >> 6, c4 = (idx & 63) * 4;
            const void* src = Qg + (size_t)(k * 8 + r) * NN + c4;
            cp16(Pb + idx * 16, src);
        }
    };

    ldchunk(0);
    asm volatile("cp.async.commit_group;" ::: "memory");
    ldchunk(1);
    asm volatile("cp.async.commit_group;" ::: "memory");

    const __half2 k1032 = __half2half2(__ushort_as_half((unsigned short)0x6408));

    for (int k = 0; k < NCHUNK; ++k) {
        const int b = k % 3;
        if (k == NCHUNK - 1) asm volatile("cp.async.wait_group 0;" ::: "memory");
        else                 asm volatile("cp.async.wait_group 1;" ::: "memory");
        __syncthreads();

        {   // dequant packed buf b -> fp16 B tile [n rows][k cols], SW128
            int g = k >> 1;
            float s = __ldg(g_S + (size_t)g * NN + n0 + tid);
            __half2 s2 = __half2half2(__float2half_rn(s));
            const int* qp = (const int*)(sm + BPK_OFF + b * 8192);
            char* bb = sm + B16_OFF + b * 32768;
#pragma unroll
            for (int r = 0; r < 8; ++r) {
                int w = qp[r * 256 + tid];
                uint32_t t0 = ((uint32_t)(w)       & 0x000F000Fu) | 0x64006400u;
                uint32_t t1 = ((uint32_t)(w >> 4)  & 0x000F000Fu) | 0x64006400u;
                uint32_t t2 = ((uint32_t)(w >> 8)  & 0x000F000Fu) | 0x64006400u;
                uint32_t t3 = ((uint32_t)(w >> 12) & 0x000F000Fu) | 0x64006400u;
                __half2 h0 = __hmul2(__hsub2(*(__half2*)&t0, k1032), s2);
                __half2 h1 = __hmul2(__hsub2(*(__half2*)&t1, k1032), s2);
                __half2 h2 = __hmul2(__hsub2(*(__half2*)&t2, k1032), s2);
                __half2 h3 = __hmul2(__hsub2(*(__half2*)&t3, k1032), s2);
                uint32_t u0 = __byte_perm(*(uint32_t*)&h0, *(uint32_t*)&h1, 0x5410);
                uint32_t u1 = __byte_perm(*(uint32_t*)&h2, *(uint32_t*)&h3, 0x5410);
                uint32_t u2 = __byte_perm(*(uint32_t*)&h0, *(uint32_t*)&h1, 0x7632);
                uint32_t u3 = __byte_perm(*(uint32_t*)&h2, *(uint32_t*)&h3, 0x7632);
                uint32_t off = SWZ((uint32_t)(tid * 128 + r * 16));
                *(uint4*)(bb + off) = make_uint4(u0, u1, u2, u3);
            }
        }
        asm volatile("tcgen05.fence::before_thread_sync;" ::: "memory");
        __syncthreads();

        if (tid < 32) {
            asm volatile("tcgen05.fence::after_thread_sync;" ::: "memory");
            if (elect_one()) {
                uint64_t ad = MAKE_DESC(smb + A_OFF + b * 16384);
                uint64_t bd = MAKE_DESC(smb + B16_OFF + b * 32768);
#pragma unroll
                for (int ks = 0; ks < 4; ++ks) {
                    uint32_t en = (k | ks) != 0;
                    asm volatile("{\n\t.reg .pred p;\n\tsetp.ne.u32 p, %4, 0;\n\t"
                                 "tcgen05.mma.cta_group::1.kind::f16 [%0], %1, %2, %3, {%5,%5,%5,%5}, p;\n\t}"
                                 :: "r"(tmem), "l"(ad + 2 * ks), "l"(bd + 2 * ks),
                                    "r"(IDESC), "r"(en), "r"(0u) : "memory");
                }
                asm volatile("tcgen05.commit.cta_group::1.mbarrier::arrive::one.shared::cluster.b64 [%0];"
                             :: "r"(smb + CTRL_OFF + 8 + b * 8) : "memory");
            }
        }

        if (k >= 1) mbar_wait(smb + CTRL_OFF + 8 + ((k - 1) % 3) * 8, ((k - 1) / 3) & 1);
        if (k + 2 < NCHUNK) {
            ldchunk(k + 2);
            asm volatile("cp.async.commit_group;" ::: "memory");
        }
    }

    mbar_wait(smb + CTRL_OFF + 8 + ((NCHUNK - 1) % 3) * 8, ((NCHUNK - 1) / 3) & 1);
    asm volatile("tcgen05.fence::after_thread_sync;" ::: "memory");

    const int w = tid >> 5, lane = tid & 31;
    const int sub = w & 3;
    const int colbase = (w >> 2) * 128;
    const int m = m0 + sub * 32 + lane;

#pragma unroll
    for (int cc = 0; cc < 4; ++cc) {
        uint32_t d[32];
        asm volatile(
            "tcgen05.ld.sync.aligned.32x32b.x32.b32 "
            "{%0,%1,%2,%3,%4,%5,%6,%7,%8,%9,%10,%11,%12,%13,%14,%15,"
            "%16,%17,%18,%19,%20,%21,%22,%23,%24,%25,%26,%27,%28,%29,%30,%31}, [%32];"
            : "=r"(d[0]), "=r"(d[1]), "=r"(d[2]), "=r"(d[3]), "=r"(d[4]), "=r"(d[5]),
              "=r"(d[6]), "=r"(d[7]), "=r"(d[8]), "=r"(d[9]), "=r"(d[10]), "=r"(d[11]),
              "=r"(d[12]), "=r"(d[13]), "=r"(d[14]), "=r"(d[15]), "=r"(d[16]), "=r"(d[17]),
              "=r"(d[18]), "=r"(d[19]), "=r"(d[20]), "=r"(d[21]), "=r"(d[22]), "=r"(d[23]),
              "=r"(d[24]), "=r"(d[25]), "=r"(d[26]), "=r"(d[27]), "=r"(d[28]), "=r"(d[29]),
              "=r"(d[30]), "=r"(d[31])
            : "r"(tmem + colbase + cc * 32));
        asm volatile("tcgen05.wait::ld.sync.aligned;" ::: "memory");

        int colstart = n0 + colbase + cc * 32;
        if (!f32m) {
            const __half2* bp = (const __half2*)biasv + (colstart >> 1);
            uint4 v[4];
            __half2* hv = (__half2*)v;
#pragma unroll
            for (int j = 0; j < 16; ++j) {
                float2 bf = __half22float2(bp[j]);
                hv[j] = __floats2half2_rn(__uint_as_float(d[2 * j]) + bf.x,
                                          __uint_as_float(d[2 * j + 1]) + bf.y);
            }
            uint4* dst = (uint4*)((__half*)outv + (size_t)m * NN + colstart);
            dst[0] = v[0]; dst[1] = v[1]; dst[2] = v[2]; dst[3] = v[3];
        } else {
            const float2* bp = (const float2*)biasv + (colstart >> 1);
            float2* dst = (float2*)((float*)outv + (size_t)m * NN + colstart);
#pragma unroll
            for (int j = 0; j < 16; ++j) {
                float2 bf = bp[j];
                dst[j] = make_float2(__uint_as_float(d[2 * j]) + bf.x,
                                     __uint_as_float(d[2 * j + 1]) + bf.y);
            }
        }
    }
    asm volatile("tcgen05.fence::before_thread_sync;" ::: "memory");
    __syncthreads();
    if (tid == 0) {
#pragma unroll
        for (int s = 0; s < 3; ++s)
            asm volatile("mbarrier.inval.shared.b64 [%0];"
                         :: "r"(smb + CTRL_OFF + 8 + s * 8) : "memory");
    }
    __syncthreads();
    if (tid < 32)
        asm volatile("tcgen05.dealloc.cta_group::1.sync.aligned.b32 %0, %1;"
                     :: "r"(tmem), "r"(512u));

#else
    // ===================== fallback: proven R4 mma.sync path =====================
    __half* As = (__half*)sm;                       // [2][BM*LDA]
    __half* Bs = As + 2 * BM * LDA;                 // [2][FBK*LDB]
    const int lane = tid & 31;
    const int warp = tid >> 5;
    const int warp_m = warp >> 1;
    const int warp_n = warp & 1;

    for (int hf = 0; hf < 2; ++hf) {
        __syncthreads();
        const int nh0 = n0 + hf * 128;
        const __half* Ag = g_A + (size_t)m0 * KK;
        const __half* Bg = g_W + nh0;

        float acc[2][8][4];
#pragma unroll
        for (int i = 0; i < 2; ++i)
#pragma unroll
            for (int j = 0; j < 8; ++j)
#pragma unroll
                for (int c = 0; c < 4; ++c) acc[i][j][c] = 0.f;

        auto load_tile = [&](int kt, int buf) {
            int k0 = kt * FBK;
#pragma unroll
            for (int i = 0; i < 2; ++i) {
                int c   = tid + i * 256;
                int row = c >> 2;
                int col = (c & 3) << 3;
                const __half* src = Ag + (size_t)row * KK + k0 + col;
                uint32_t dst = (uint32_t)__cvta_generic_to_shared(
                    &As[buf * BM * LDA + row * LDA + col]);
                cp16(dst, src);
            }
#pragma unroll
            for (int i = 0; i < 2; ++i) {
                int c   = tid + i * 256;
                int row = c >> 4;
                int col = (c & 15) << 3;
                const __half* src = Bg + (size_t)(k0 + row) * NN + col;
                uint32_t dst = (uint32_t)__cvta_generic_to_shared(
                    &Bs[buf * FBK * LDB + row * LDB + col]);
                cp16(dst, src);
            }
        };

        load_tile(0, 0);
        asm volatile("cp.async.commit_group;\n" ::: "memory");

        const int KT = KK / FBK;
        int buf = 0;
        for (int kt = 0; kt < KT; ++kt) {
            if (kt + 1 < KT) {
                load_tile(kt + 1, buf ^ 1);
                asm volatile("cp.async.commit_group;\n" ::: "memory");
                asm volatile("cp.async.wait_group 1;\n" ::: "memory");
            } else {
                asm volatile("cp.async.wait_group 0;\n" ::: "memory");
            }
            __syncthreads();

#pragma unroll
            for (int ks = 0; ks < 2; ++ks) {
                uint32_t a[2][4], b[8][2];
#pragma unroll
                for (int mi = 0; mi < 2; ++mi) {
                    int row = warp_m * 32 + mi * 16 + (lane & 15);
                    int col = ks * 16 + ((lane >> 4) << 3);
                    uint32_t addr = (uint32_t)__cvta_generic_to_shared(
                        &As[buf * BM * LDA + row * LDA + col]);
                    asm volatile(
                        "ldmatrix.sync.aligned.m8n8.x4.shared.b16 {%0,%1,%2,%3}, [%4];\n"
                        : "=r"(a[mi][0]), "=r"(a[mi][1]), "=r"(a[mi][2]), "=r"(a[mi][3])
                        : "r"(addr));
                }
#pragma unroll
                for (int nb2 = 0; nb2 < 4; ++nb2) {
                    int row = ks * 16 + (lane & 15);
                    int col = warp_n * 64 + nb2 * 16 + ((lane >> 4) << 3);
                    uint32_t addr = (uint32_t)__cvta_generic_to_shared(
                        &Bs[buf * FBK * LDB + row * LDB + col]);
                    asm volatile(
                        "ldmatrix.sync.aligned.m8n8.x4.trans.shared.b16 {%0,%1,%2,%3}, [%4];\n"
                        : "=r"(b[2 * nb2][0]), "=r"(b[2 * nb2][1]),
                          "=r"(b[2 * nb2 + 1][0]), "=r"(b[2 * nb2 + 1][1])
                        : "r"(addr));
                }
#pragma unroll
                for (int mi = 0; mi < 2; ++mi)
#pragma unroll
                    for (int ni = 0; ni < 8; ++ni) {
                        asm volatile(
                            "mma.sync.aligned.m16n8k16.row.col.f32.f16.f16.f32 "
                            "{%0,%1,%2,%3}, {%4,%5,%6,%7}, {%8,%9}, {%0,%1,%2,%3};\n"
                            : "+f"(acc[mi][ni][0]), "+f"(acc[mi][ni][1]),
                              "+f"(acc[mi][ni][2]), "+f"(acc[mi][ni][3])
                            : "r"(a[mi][0]), "r"(a[mi][1]), "r"(a[mi][2]), "r"(a[mi][3]),
                              "r"(b[ni][0]), "r"(b[ni][1]));
                    }
            }
            __syncthreads();
            buf ^= 1;
        }

#pragma unroll
        for (int mi = 0; mi < 2; ++mi) {
#pragma unroll
            for (int ni = 0; ni < 8; ++ni) {
                int row0 = m0 + warp_m * 32 + mi * 16 + (lane >> 2);
                int col  = nh0 + warp_n * 64 + ni * 8 + (lane & 3) * 2;
                float bx, by;
                if (f32m) {
                    const float* bp = (const float*)biasv + col;
                    bx = bp[0]; by = bp[1];
                } else {
                    __half2 bv = *reinterpret_cast<const __half2*>((const __half*)biasv + col);
                    float2 b2 = __half22float2(bv);
                    bx = b2.x; by = b2.y;
                }
                float v00 = acc[mi][ni][0] + bx, v01 = acc[mi][ni][1] + by;
                float v10 = acc[mi][ni][2] + bx, v11 = acc[mi][ni][3] + by;
                if (f32m) {
                    float* op = (float*)outv;
                    *reinterpret_cast<float2*>(&op[(size_t)row0 * NN + col]) =
                        make_float2(v00, v01);
                    *reinterpret_cast<float2*>(&op[(size_t)(row0 + 8) * NN + col]) =
                        make_float2(v10, v11);
                } else {
                    __half* op = (__half*)outv;
                    *reinterpret_cast<__half2*>(&op[(size_t)row0 * NN + col]) =
                        __floats2half2_rn(v00, v01);
                    *reinterpret_cast<__half2*>(&op[(size_t)(row0 + 8) * NN + col]) =
                        __floats2half2_rn(v10, v11);
                }
            }
        }
    }
#endif
}

// ---------------------------------------------------------------------------
extern "C" void kernel_launch(void* const* d_in, const int* in_sizes, int n_in,
                              void* d_out, int out_size) {
    const void* input   = d_in[0];              // [M, K] fp16 (or fp32-upcast)
    const int*  qw      = (const int*)d_in[1];  // [K/8, N] int32
    const int*  qs      = (const int*)d_in[2];  // [G, N/8] int32
    const void* qsm     = d_in[3];              // [G] fp16 (or fp32-upcast)
    const int*  invperm = (const int*)d_in[4];  // [K] int32
    const void* bias    = d_in[5];              // [N] fp16 (or fp32-upcast)

    probe_arch<<<1, 1>>>();
    probe_dtype<<<1, 32>>>(qsm);
    build_perm<<<KK / 256, 256>>>(invperm);
    permute_act<<<(MM * KK) / 256, 256>>>(input);
    build_scales<<<(GG * NN) / 256, 256>>>(qs, qsm);
    dequant_w<<<((KK / 8) * NN) / 256, 256>>>(qw);   // no-op when tcgen05 active

    cudaFuncSetAttribute(gemm_tc, cudaFuncAttributeMaxDynamicSharedMemorySize,
                         SMEM_BYTES);
    gemm_tc<<<(MM / BM) * (NN / BN), 256, SMEM_BYTES>>>(d_out, bias, qw);
}

// round 12
// speedup vs baseline: 1.6545x; 1.1381x over previous
#include <cuda_runtime.h>
#include <cuda_fp16.h>
#include <cstdint>

#define MM 4096
#define KK 4096
#define NN 12288
#define GG 32            // K / 128 groups
#define NCHUNK 64        // K / 64

#define BM 128
#define BN 256

// ---- dynamic smem layout (tcgen05 path) ----
#define B16_OFF  0                       // 3 x 32768 (fp16 B tiles, SW128)
#define A_OFF    (3*32768)               // 3 x 16384 (fp16 A tiles, SW128)
#define BPK_OFF  (A_OFF + 3*16384)       // 3 x 8192  (packed B words)
#define CTRL_OFF (BPK_OFF + 3*8192)      // tmem ptr + 3 mbarriers
#define SMEM_BYTES (CTRL_OFF + 64)

#define SWZ(x) ((x) ^ (((x) >> 3) & 0x70))
#define IDESC ((1u << 4) | ((BN / 8) << 17) | ((BM / 16) << 24))  // f32 acc, f16 in

// SW128 K-major smem descriptor (LBO=1, SBO=64, version=1, layout=2)
#define DESC_BASE ((uint64_t(2) << 61) | (uint64_t(1) << 46) | \
                   (uint64_t(64) << 32) | (uint64_t(1) << 16))
#define MAKE_DESC(a) (DESC_BASE | ((uint64_t)((a) >> 4) & 0x3FFF))

// nibble interleave: A position p within each 8-k group reads nibble ilv(p)
__host__ __device__ __forceinline__ int ilvf(int p) {
    return ((p >> 1) | ((p & 1) << 2));
}

// Scratch
__device__ __half g_A[(size_t)MM * KK];   // permuted+interleaved activations [M, K]
__device__ float  g_S[(size_t)GG * NN];   // group scales (g, n)
__device__ int    g_perm[KK];
__device__ int    g_f32;                  // 1 if fp16 tensors arrive upcast to fp32

// ---------------------------------------------------------------------------
__global__ void probe_dtype(const void* __restrict__ qsm) {
    if (threadIdx.x == 0) {
        const float* f = (const float*)qsm;
        int ok = 1;
#pragma unroll
        for (int i = 0; i < 16; ++i) {
            float v = f[i];
            if (!(v > 1e-8f && v < 0.004f)) ok = 0;
        }
        g_f32 = ok;
    }
}

__global__ void build_perm(const int* __restrict__ invperm) {
    int j = blockIdx.x * blockDim.x + threadIdx.x;
    if (j < KK) g_perm[invperm[j]] = j;
}

// g_A[m, k'] = x[m, perm[(k' & ~7) | ilv(k' & 7)]]  (4 elems/thread, vector store)
__global__ void permute_act(const void* __restrict__ inp) {
    int t = blockIdx.x * blockDim.x + threadIdx.x;   // MM*KK/4 threads
    int base = t * 4;
    int m = base >> 12;
    int k0 = base & (KK - 1);
    const int mrow = m << 12;
    int src[4];
#pragma unroll
    for (int j = 0; j < 4; ++j) {
        int k = k0 + j;
        src[j] = g_perm[(k & ~7) | ilvf(k & 7)];
    }
    __half v[4];
    if (g_f32) {
        const float* x = (const float*)inp + mrow;
#pragma unroll
        for (int j = 0; j < 4; ++j) v[j] = __float2half(x[src[j]]);
    } else {
        const __half* x = (const __half*)inp + mrow;
#pragma unroll
        for (int j = 0; j < 4; ++j) v[j] = x[src[j]];
    }
    *(uint2*)(g_A + base) = *(uint2*)v;
}

// s[g, n] = (scode + 1)^2 * scale_max[g]
__global__ void build_scales(const int* __restrict__ qs, const void* __restrict__ qsm) {
    int idx = blockIdx.x * blockDim.x + threadIdx.x;
    int n = idx % NN;
    int g = idx / NN;
    float smax = g_f32 ? ((const float*)qsm)[g]
                       : __half2float(((const __half*)qsm)[g]);
    int sq = qs[g * (NN / 8) + (n >> 3)];
    int sc = (sq >> ((n & 7) * 4)) & 0xF;
    g_S[idx] = (float)((sc + 1) * (sc + 1)) * smax;
}

// ---------------------------------------------------------------------------
__device__ __forceinline__ uint32_t elect_one() {
    uint32_t p;
    asm volatile("{.reg .pred p; elect.sync _|p, 0xFFFFFFFF; selp.b32 %0,1,0,p;}"
                 : "=r"(p));
    return p;
}
__device__ __forceinline__ void cp16(uint32_t dst, const void* src) {
    asm volatile("cp.async.cg.shared.global [%0], [%1], 16;\n" :: "r"(dst), "l"(src));
}
__device__ __forceinline__ void mbar_wait(uint32_t a, uint32_t par) {
    uint32_t done;
    asm volatile("{.reg .pred p; mbarrier.try_wait.parity.acquire.cta.shared::cta.b64 p, [%1], %2;"
                 " selp.b32 %0,1,0,p;}" : "=r"(done) : "r"(a), "r"(par) : "memory");
    if (!done) {
        asm volatile("{.reg .pred P1; WL_%=: mbarrier.try_wait.parity.acquire.cta.shared::cta.b64 P1, [%0], %1, 0x989680;"
                     " @P1 bra.uni WD_%=; bra.uni WL_%=; WD_%=:}"
                     :: "r"(a), "r"(par) : "memory");
    }
}

// ---------------------------------------------------------------------------
// One CTA = 128x256 output tile, 512 threads.
__global__ __launch_bounds__(512, 1) __cluster_dims__(1, 1, 1)
void gemm_tc(void* __restrict__ outv, const void* __restrict__ biasv,
             const int* __restrict__ qw) {
    extern __shared__ __align__(1024) char sm[];
    const int tid = threadIdx.x;
    const int bid = blockIdx.x;
    const int nb = bid % (NN / BN);
    const int mb = bid / (NN / BN);
    const int n0 = nb * BN;
    const int m0 = mb * BM;
    const int f32m = g_f32;

#ifdef __CUDA_ARCH_FEAT_SM103_ALL
    // ===================== tcgen05 fused-dequant path =====================
    const uint32_t smb = (uint32_t)__cvta_generic_to_shared(sm);
    if (tid < 32) {
        asm volatile("tcgen05.alloc.cta_group::1.sync.aligned.shared::cta.b32 [%0], %1;"
                     :: "r"(smb + CTRL_OFF), "r"(512u) : "memory");
        asm volatile("tcgen05.relinquish_alloc_permit.cta_group::1.sync.aligned;");
    }
    if (tid == 0) {
#pragma unroll
        for (int s = 0; s < 3; ++s)
            asm volatile("mbarrier.init.shared.b64 [%0], %1;"
                         :: "r"(smb + CTRL_OFF + 8 + s * 8), "r"(1u) : "memory");
    }
    __syncthreads();
    uint32_t tmem;
    asm volatile("ld.shared.b32 %0, [%1];" : "=r"(tmem) : "r"(smb + CTRL_OFF));

    const __half* Ag = g_A + (size_t)m0 * KK;
    const int*    Qg = qw + n0;

    auto ldchunk = [&](int k) {
        int b = k % 3;
        uint32_t Ab = smb + A_OFF + b * 16384;
#pragma unroll
        for (int i = 0; i < 2; ++i) {
            int idx = tid + i * 512;            // 0..1023
            int row = idx >> 3, c16 = idx & 7;
            const void* src = Ag + (size_t)row * KK + k * 64 + c16 * 8;
            uint32_t off = (uint32_t)(row * 128 + c16 * 16);
            cp16(Ab + SWZ(off), src);
        }
        uint32_t Pb = smb + BPK_OFF + b * 8192;
        {
            int idx = tid;                      // 0..511
            int r = idx >> 6, c4 = (idx & 63) * 4;
            const void* src = Qg + (size_t)(k * 8 + r) * NN + c4;
            cp16(Pb + idx * 16, src);
        }
    };

    ldchunk(0);
    asm volatile("cp.async.commit_group;" ::: "memory");
    ldchunk(1);
    asm volatile("cp.async.commit_group;" ::: "memory");

    const __half2 k1032 = __half2half2(__ushort_as_half((unsigned short)0x6408));
    const int dq_n = tid & 255;                 // n column this thread dequants
    const int dq_r0 = (tid >> 8) * 4;           // first of 4 packed rows

    for (int k = 0; k < NCHUNK; ++k) {
        const int b = k % 3;
        if (k == NCHUNK - 1) asm volatile("cp.async.wait_group 0;" ::: "memory");
        else                 asm volatile("cp.async.wait_group 1;" ::: "memory");
        __syncthreads();

        {   // dequant packed buf b -> fp16 B tile [n][k], SW128 (interleaved k)
            int g = k >> 1;
            float s = __ldg(g_S + (size_t)g * NN + n0 + dq_n);
            __half2 s2 = __half2half2(__float2half_rn(s));
            const int* qp = (const int*)(sm + BPK_OFF + b * 8192);
            char* bb = sm + B16_OFF + b * 32768;
#pragma unroll
            for (int rr = 0; rr < 4; ++rr) {
                int r = dq_r0 + rr;
                int w = qp[r * 256 + dq_n];
                uint32_t t0 = ((uint32_t)(w)       & 0x000F000Fu) | 0x64006400u;
                uint32_t t1 = ((uint32_t)(w >> 4)  & 0x000F000Fu) | 0x64006400u;
                uint32_t t2 = ((uint32_t)(w >> 8)  & 0x000F000Fu) | 0x64006400u;
                uint32_t t3 = ((uint32_t)(w >> 12) & 0x000F000Fu) | 0x64006400u;
                __half2 h0 = __hmul2(__hsub2(*(__half2*)&t0, k1032), s2);
                __half2 h1 = __hmul2(__hsub2(*(__half2*)&t1, k1032), s2);
                __half2 h2 = __hmul2(__hsub2(*(__half2*)&t2, k1032), s2);
                __half2 h3 = __hmul2(__hsub2(*(__half2*)&t3, k1032), s2);
                uint32_t off = SWZ((uint32_t)(dq_n * 128 + r * 16));
                *(uint4*)(bb + off) = make_uint4(*(uint32_t*)&h0, *(uint32_t*)&h1,
                                                 *(uint32_t*)&h2, *(uint32_t*)&h3);
            }
        }
        asm volatile("tcgen05.fence::before_thread_sync;" ::: "memory");
        __syncthreads();

        if (tid < 32) {
            asm volatile("tcgen05.fence::after_thread_sync;" ::: "memory");
            if (elect_one()) {
                uint64_t ad = MAKE_DESC(smb + A_OFF + b * 16384);
                uint64_t bd = MAKE_DESC(smb + B16_OFF + b * 32768);
#pragma unroll
                for (int ks = 0; ks < 4; ++ks) {
                    uint32_t en = (k | ks) != 0;
                    asm volatile("{\n\t.reg .pred p;\n\tsetp.ne.u32 p, %4, 0;\n\t"
                                 "tcgen05.mma.cta_group::1.kind::f16 [%0], %1, %2, %3, {%5,%5,%5,%5}, p;\n\t}"
                                 :: "r"(tmem), "l"(ad + 2 * ks), "l"(bd + 2 * ks),
                                    "r"(IDESC), "r"(en), "r"(0u) : "memory");
                }
                asm volatile("tcgen05.commit.cta_group::1.mbarrier::arrive::one.shared::cluster.b64 [%0];"
                             :: "r"(smb + CTRL_OFF + 8 + b * 8) : "memory");
            }
        }

        if (k >= 1) mbar_wait(smb + CTRL_OFF + 8 + ((k - 1) % 3) * 8, ((k - 1) / 3) & 1);
        if (k + 2 < NCHUNK) {
            ldchunk(k + 2);
            asm volatile("cp.async.commit_group;" ::: "memory");
        }
    }

    mbar_wait(smb + CTRL_OFF + 8 + ((NCHUNK - 1) % 3) * 8, ((NCHUNK - 1) / 3) & 1);
    asm volatile("tcgen05.fence::after_thread_sync;" ::: "memory");

    // epilogue: 16 warps; warp w -> subpartition (w&3), col group (w>>2)*64
    const int w = tid >> 5, lane = tid & 31;
    const int sub = w & 3;
    const int colbase = (w >> 2) * 64;
    const int m = m0 + sub * 32 + lane;

#pragma unroll
    for (int cc = 0; cc < 2; ++cc) {
        uint32_t d[32];
        asm volatile(
            "tcgen05.ld.sync.aligned.32x32b.x32.b32 "
            "{%0,%1,%2,%3,%4,%5,%6,%7,%8,%9,%10,%11,%12,%13,%14,%15,"
            "%16,%17,%18,%19,%20,%21,%22,%23,%24,%25,%26,%27,%28,%29,%30,%31}, [%32];"
            : "=r"(d[0]), "=r"(d[1]), "=r"(d[2]), "=r"(d[3]), "=r"(d[4]), "=r"(d[5]),
              "=r"(d[6]), "=r"(d[7]), "=r"(d[8]), "=r"(d[9]), "=r"(d[10]), "=r"(d[11]),
              "=r"(d[12]), "=r"(d[13]), "=r"(d[14]), "=r"(d[15]), "=r"(d[16]), "=r"(d[17]),
              "=r"(d[18]), "=r"(d[19]), "=r"(d[20]), "=r"(d[21]), "=r"(d[22]), "=r"(d[23]),
              "=r"(d[24]), "=r"(d[25]), "=r"(d[26]), "=r"(d[27]), "=r"(d[28]), "=r"(d[29]),
              "=r"(d[30]), "=r"(d[31])
            : "r"(tmem + colbase + cc * 32));
        asm volatile("tcgen05.wait::ld.sync.aligned;" ::: "memory");

        int colstart = n0 + colbase + cc * 32;
        if (!f32m) {
            const __half2* bp = (const __half2*)biasv + (colstart >> 1);
            uint4 v[4];
            __half2* hv = (__half2*)v;
#pragma unroll
            for (int j = 0; j < 16; ++j) {
                float2 bf = __half22float2(bp[j]);
                hv[j] = __floats2half2_rn(__uint_as_float(d[2 * j]) + bf.x,
                                          __uint_as_float(d[2 * j + 1]) + bf.y);
            }
            uint4* dst = (uint4*)((__half*)outv + (size_t)m * NN + colstart);
            dst[0] = v[0]; dst[1] = v[1]; dst[2] = v[2]; dst[3] = v[3];
        } else {
            const float2* bp = (const float2*)biasv + (colstart >> 1);
            float2* dst = (float2*)((float*)outv + (size_t)m * NN + colstart);
#pragma unroll
            for (int j = 0; j < 16; ++j) {
                float2 bf = bp[j];
                dst[j] = make_float2(__uint_as_float(d[2 * j]) + bf.x,
                                     __uint_as_float(d[2 * j + 1]) + bf.y);
            }
        }
    }
    asm volatile("tcgen05.fence::before_thread_sync;" ::: "memory");
    __syncthreads();
    if (tid == 0) {
#pragma unroll
        for (int s = 0; s < 3; ++s)
            asm volatile("mbarrier.inval.shared.b64 [%0];"
                         :: "r"(smb + CTRL_OFF + 8 + s * 8) : "memory");
    }
    __syncthreads();
    if (tid < 32)
        asm volatile("tcgen05.dealloc.cta_group::1.sync.aligned.b32 %0, %1;"
                     :: "r"(tmem), "r"(512u));

#else
    // ============ compile-pass fallback (never runs on sm_103a) ============
    // Naive but correct: each thread computes 64 outputs from g_A (interleaved
    // k order) and packed weights directly.
    for (int e = tid; e < BM * BN; e += 512) {
        int mr = m0 + (e >> 8);          // BN = 256
        int n  = n0 + (e & 255);
        float acc;
        if (f32m) acc = ((const float*)biasv)[n];
        else      acc = __half2float(((const __half*)biasv)[n]);
        const __half* Arow = g_A + (size_t)mr * KK;
        for (int kp = 0; kp < KK; kp += 8) {
            int word = qw[(size_t)(kp >> 3) * NN + n];
            float s = g_S[(size_t)(kp >> 7) * NN + n];
#pragma unroll
            for (int p = 0; p < 8; ++p) {
                int nib = (word >> (ilvf(p) * 4)) & 0xF;
                acc += __half2float(Arow[kp + p]) * (float)(nib - 8) * s;
            }
        }
        if (f32m) ((float*)outv)[(size_t)mr * NN + n] = acc;
        else      ((__half*)outv)[(size_t)mr * NN + n] = __float2half(acc);
    }
#endif
}

// ---------------------------------------------------------------------------
extern "C" void kernel_launch(void* const* d_in, const int* in_sizes, int n_in,
                              void* d_out, int out_size) {
    const void* input   = d_in[0];              // [M, K] fp16 (or fp32-upcast)
    const int*  qw      = (const int*)d_in[1];  // [K/8, N] int32
    const int*  qs      = (const int*)d_in[2];  // [G, N/8] int32
    const void* qsm     = d_in[3];              // [G] fp16 (or fp32-upcast)
    const int*  invperm = (const int*)d_in[4];  // [K] int32
    const void* bias    = d_in[5];              // [N] fp16 (or fp32-upcast)

    probe_dtype<<<1, 32>>>(qsm);
    build_perm<<<KK / 256, 256>>>(invperm);
    permute_act<<<(MM * KK / 4) / 256, 256>>>(input);
    build_scales<<<(GG * NN) / 256, 256>>>(qs, qsm);

    cudaFuncSetAttribute(gemm_tc, cudaFuncAttributeMaxDynamicSharedMemorySize,
                         SMEM_BYTES);
    gemm_tc<<<(MM / BM) * (NN / BN), 512, SMEM_BYTES>>>(d_out, bias, qw);
}